// round 3
// baseline (speedup 1.0000x reference)
#include <cuda_runtime.h>
#include <cstdint>
#include <math.h>

#define Bb 128
#define Tt 1024
#define Nn 256
#define Mm 256
#define Gg 768
#define ROWS (Bb*Tt)

// Scratch (allocation-free rule: __device__ globals)
__device__ float g_gx[(size_t)ROWS * Gg];    // 402.7 MB: input-gate activations for current layer
__device__ float g_out0[(size_t)ROWS * Mm];  // 134.2 MB: layer-0 output

// ---------------- cluster / DSMEM helpers ----------------
__device__ __forceinline__ uint32_t smem_u32(const void* p) {
    uint32_t a;
    asm("{ .reg .u64 t; cvta.to.shared.u64 t, %1; cvt.u32.u64 %0, t; }" : "=r"(a) : "l"(p));
    return a;
}
__device__ __forceinline__ uint32_t cl_rank() {
    uint32_t r; asm("mov.u32 %0, %%cluster_ctarank;" : "=r"(r)); return r;
}
__device__ __forceinline__ uint32_t cl_map(uint32_t addr, uint32_t rank) {
    uint32_t r; asm("mapa.shared::cluster.u32 %0, %1, %2;" : "=r"(r) : "r"(addr), "r"(rank)); return r;
}
__device__ __forceinline__ void st_cl_f32(uint32_t addr, float v) {
    asm volatile("st.shared::cluster.f32 [%0], %1;" :: "r"(addr), "f"(v) : "memory");
}
__device__ __forceinline__ void cl_sync() {
    asm volatile("barrier.cluster.arrive.aligned;" ::: "memory");
    asm volatile("barrier.cluster.wait.aligned;" ::: "memory");
}

// ---------------- input-gate GEMM ----------------
// C[r,g] = sum_k A[r,k] * W[g,k] + bias[g]
// A: [131072, 256] row-major (K contiguous). W: [768, 256] row-major. C: [131072, 768].
// Tile 128(rows) x 64(gates), BK=16, 256 threads, 8x4 register blocking.
__global__ __launch_bounds__(256) void gemm_gates(
    const float* __restrict__ A, const float* __restrict__ W,
    const float* __restrict__ bias, float* __restrict__ C)
{
    __shared__ float As[16 * 132];  // [k][row], padded stride 132 to dodge conflicts
    __shared__ float Ws[16 * 68];   // [k][g],   padded stride 68

    const int tid  = threadIdx.x;
    const int row0 = blockIdx.y * 128;
    const int g0   = blockIdx.x * 64;
    const int lr   = tid >> 2;   // 0..63
    const int kq   = tid & 3;    // 0..3  (4 k-floats each)
    const int tx   = tid & 15;   // gate group
    const int ty   = tid >> 4;   // row group

    float acc[8][4];
#pragma unroll
    for (int i = 0; i < 8; ++i)
#pragma unroll
        for (int j = 0; j < 4; ++j) acc[i][j] = 0.f;

    for (int k0 = 0; k0 < 256; k0 += 16) {
        float4 a0 = *(const float4*)(A + (size_t)(row0 + lr)      * 256 + k0 + kq * 4);
        float4 a1 = *(const float4*)(A + (size_t)(row0 + lr + 64) * 256 + k0 + kq * 4);
        float4 w0 = *(const float4*)(W + (size_t)(g0 + lr)        * 256 + k0 + kq * 4);
        __syncthreads();
        As[(kq*4+0)*132 + lr] = a0.x;
        As[(kq*4+1)*132 + lr] = a0.y;
        As[(kq*4+2)*132 + lr] = a0.z;
        As[(kq*4+3)*132 + lr] = a0.w;
        As[(kq*4+0)*132 + lr + 64] = a1.x;
        As[(kq*4+1)*132 + lr + 64] = a1.y;
        As[(kq*4+2)*132 + lr + 64] = a1.z;
        As[(kq*4+3)*132 + lr + 64] = a1.w;
        Ws[(kq*4+0)*68 + lr] = w0.x;
        Ws[(kq*4+1)*68 + lr] = w0.y;
        Ws[(kq*4+2)*68 + lr] = w0.z;
        Ws[(kq*4+3)*68 + lr] = w0.w;
        __syncthreads();
#pragma unroll
        for (int k = 0; k < 16; ++k) {
            float ra[8], rw[4];
            *(float4*)(ra)     = *(const float4*)(As + k*132 + ty*8);
            *(float4*)(ra + 4) = *(const float4*)(As + k*132 + ty*8 + 4);
            *(float4*)(rw)     = *(const float4*)(Ws + k*68  + tx*4);
#pragma unroll
            for (int i = 0; i < 8; ++i)
#pragma unroll
                for (int j = 0; j < 4; ++j)
                    acc[i][j] = fmaf(ra[i], rw[j], acc[i][j]);
        }
    }
    float4 bv = *(const float4*)(bias + g0 + tx*4);
#pragma unroll
    for (int i = 0; i < 8; ++i) {
        float4 o;
        o.x = acc[i][0] + bv.x; o.y = acc[i][1] + bv.y;
        o.z = acc[i][2] + bv.z; o.w = acc[i][3] + bv.w;
        *(float4*)(C + (size_t)(row0 + ty*8 + i) * 768 + g0 + tx*4) = o;
    }
}

// ---------------- GRU recurrence ----------------
// Cluster of 4 CTAs owns 4 batch rows. CTA rank owns h columns [rank*64, rank*64+64).
// SMEM holds its 192 w_hh gate-rows (3 gates x 64 cols x 256 k = 192KB) for all 1024 steps.
// Per step: 12 dot warps (2-way K split, balanced 3/SMSP) -> stage gh -> epilogue warps
// compute gates & h_new -> DSMEM-broadcast h chunk to all 4 CTAs -> cluster barrier.
__global__ __launch_bounds__(512, 1) __cluster_dims__(4, 1, 1)
void gru_rec(const float* __restrict__ gx, const float* __restrict__ Whh,
             const float* __restrict__ bhh, float* __restrict__ out,
             float* __restrict__ hid)
{
    extern __shared__ float smem[];
    float4* sW4 = (float4*)smem;        // [gate(3)][kchunk(64)][col(64)] float4 = 192KB
    float*  sH  = smem + 49152;         // double-buffered h: [2][4 rows][256]
    float*  sGh = smem + 51200;         // gh partials: [2 khalf][3 gate][4 row][64 col]

    const uint32_t rank = cl_rank();
    const int b0  = (blockIdx.x >> 2) * 4;
    const int tid = threadIdx.x;

    // one-time: load this CTA's w_hh chunk into SMEM as [g][kc][col] float4
    for (int idx = tid; idx < 12288; idx += 512) {
        int g  = idx >> 12;
        int kc = (idx >> 6) & 63;
        int j  = idx & 63;
        int grow = g * 256 + (int)rank * 64 + j;
        sW4[idx] = ((const float4*)Whh)[grow * 64 + kc];
    }
    for (int i = tid; i < 2048; i += 512) sH[i] = 0.f;

    // dot-phase mapping (tid < 384): 192 gate-rows x 2 k-halves
    const int khalf = tid / 192;
    const int gg    = (tid % 192) >> 6;  // gate 0..2
    const int jj    = tid & 63;          // column within chunk
    float biasReg = 0.f;
    if (tid < 192) biasReg = bhh[gg * 256 + (int)rank * 64 + jj];  // only khalf==0 carries bias

    // epilogue mapping (tid < 256): (row, col)
    const int erow = (tid >> 6) & 3;
    const int ecol = tid & 63;

    cl_sync();  // all CTAs' h buffers zeroed + weights loaded before anyone steps

    float* hPrev = sH;
    float* hNext = sH + 1024;

    for (int t = 0; t < 1024; ++t) {
        // prefetch gx for this step (independent of h; hides DRAM latency under dots)
        float gxr = 0.f, gxz = 0.f, gxn = 0.f;
        if (tid < 256) {
            size_t base = ((size_t)(b0 + erow) * 1024 + t) * 768 + rank * 64 + ecol;
            gxr = gx[base];
            gxz = gx[base + 256];
            gxn = gx[base + 512];
        }

        if (tid < 384) {
            const float4* wp  = sW4 + gg * 4096 + jj;
            const float4* hp4 = ((const float4*)hPrev) + khalf * 32;
            float a0 = biasReg, a1 = biasReg, a2 = biasReg, a3 = biasReg;
#pragma unroll 8
            for (int kc = 0; kc < 32; ++kc) {
                float4 wv = wp[(khalf * 32 + kc) * 64];
                float4 h0 = hp4[kc];
                float4 h1 = hp4[64  + kc];
                float4 h2 = hp4[128 + kc];
                float4 h3 = hp4[192 + kc];
                a0 = fmaf(wv.x,h0.x,fmaf(wv.y,h0.y,fmaf(wv.z,h0.z,fmaf(wv.w,h0.w,a0))));
                a1 = fmaf(wv.x,h1.x,fmaf(wv.y,h1.y,fmaf(wv.z,h1.z,fmaf(wv.w,h1.w,a1))));
                a2 = fmaf(wv.x,h2.x,fmaf(wv.y,h2.y,fmaf(wv.z,h2.z,fmaf(wv.w,h2.w,a2))));
                a3 = fmaf(wv.x,h3.x,fmaf(wv.y,h3.y,fmaf(wv.z,h3.z,fmaf(wv.w,h3.w,a3))));
            }
            sGh[khalf*768 + (gg*4+0)*64 + jj] = a0;
            sGh[khalf*768 + (gg*4+1)*64 + jj] = a1;
            sGh[khalf*768 + (gg*4+2)*64 + jj] = a2;
            sGh[khalf*768 + (gg*4+3)*64 + jj] = a3;
        }
        __syncthreads();

        if (tid < 256) {
            const int o = erow * 64 + ecol;
            float ghr = sGh[o]        + sGh[768  + o];
            float ghz = sGh[256 + o]  + sGh[1024 + o];
            float ghn = sGh[512 + o]  + sGh[1280 + o];
            float r  = 1.f / (1.f + expf(-(gxr + ghr)));
            float z  = 1.f / (1.f + expf(-(gxz + ghz)));
            float hp = hPrev[erow * 256 + rank * 64 + ecol];
            float n  = tanhf(fmaf(r, ghn, gxn));
            float hnew = fmaf(z, hp - n, n);   // (1-z)*n + z*hp

            out[((size_t)(b0 + erow) * 1024 + t) * 256 + rank * 64 + ecol] = hnew;

            // broadcast new h element into every cluster CTA's hNext (incl. self)
            uint32_t laddr = smem_u32(hNext + erow * 256 + rank * 64 + ecol);
#pragma unroll
            for (int pr = 0; pr < 4; ++pr)
                st_cl_f32(cl_map(laddr, (uint32_t)pr), hnew);
        }
        cl_sync();  // release/acquire: DSMEM writes visible, hPrev readers done
        float* tmpp = hPrev; hPrev = hNext; hNext = tmpp;
    }

    if (tid < 256)
        hid[(size_t)(b0 + erow) * 256 + rank * 64 + ecol] =
            hPrev[erow * 256 + rank * 64 + ecol];
}

// ---------------- launch ----------------
extern "C" void kernel_launch(void* const* d_in, const int* in_sizes, int n_in,
                              void* d_out, int out_size)
{
    const float* X      = (const float*)d_in[0];
    const float* w_ih_0 = (const float*)d_in[1];
    const float* w_hh_0 = (const float*)d_in[2];
    const float* b_ih_0 = (const float*)d_in[3];
    const float* b_hh_0 = (const float*)d_in[4];
    const float* w_ih_1 = (const float*)d_in[5];
    const float* w_hh_1 = (const float*)d_in[6];
    const float* b_ih_1 = (const float*)d_in[7];
    const float* b_hh_1 = (const float*)d_in[8];

    float* out1 = (float*)d_out;                       // [B,T,M]
    float* hid  = out1 + (size_t)ROWS * Mm;            // [2,B,M]

    float* gx = nullptr;
    float* o0 = nullptr;
    cudaGetSymbolAddress((void**)&gx, g_gx);
    cudaGetSymbolAddress((void**)&o0, g_out0);

    const size_t REC_SMEM = 210944;  // 192KB weights + 8KB h + 6KB gh staging
    cudaFuncSetAttribute(gru_rec, cudaFuncAttributeMaxDynamicSharedMemorySize,
                         (int)REC_SMEM);

    dim3 ggrid(12, 1024);  // gates x row-tiles

    // layer 0
    gemm_gates<<<ggrid, 256>>>(X, w_ih_0, b_ih_0, gx);
    gru_rec<<<128, 512, REC_SMEM>>>(gx, w_hh_0, b_hh_0, o0, hid);
    // layer 1
    gemm_gates<<<ggrid, 256>>>(o0, w_ih_1, b_ih_1, gx);
    gru_rec<<<128, 512, REC_SMEM>>>(gx, w_hh_1, b_hh_1, out1, hid + (size_t)Bb * Mm);
}

// round 6
// speedup vs baseline: 1.2321x; 1.2321x over previous
#include <cuda_runtime.h>
#include <cstdint>
#include <math.h>

#define Bb 128
#define Tt 1024
#define Nn 256
#define Mm 256
#define Gg 768
#define ROWS (Bb*Tt)

// Scratch (allocation-free rule: __device__ globals)
__device__ float g_gx[(size_t)ROWS * Gg];    // input-gate activations for current layer
__device__ float g_out0[(size_t)ROWS * Mm];  // layer-0 output

// ---------------- packed f32x2 helpers (Blackwell FFMA2) ----------------
typedef unsigned long long u64t;

__device__ __forceinline__ u64t ffma2(u64t a, u64t b, u64t c) {
    u64t d;
    asm("fma.rn.f32x2 %0, %1, %2, %3;" : "=l"(d) : "l"(a), "l"(b), "l"(c));
    return d;
}
__device__ __forceinline__ u64t pack2(float lo, float hi) {
    u64t d; asm("mov.b64 %0, {%1, %2};" : "=l"(d) : "f"(lo), "f"(hi)); return d;
}
__device__ __forceinline__ float2 unpack2(u64t v) {
    float2 r; asm("mov.b64 {%0, %1}, %2;" : "=f"(r.x), "=f"(r.y) : "l"(v)); return r;
}

// ---------------- cluster / DSMEM helpers ----------------
__device__ __forceinline__ uint32_t smem_u32(const void* p) {
    uint32_t a;
    asm("{ .reg .u64 t; cvta.to.shared.u64 t, %1; cvt.u32.u64 %0, t; }" : "=r"(a) : "l"(p));
    return a;
}
__device__ __forceinline__ uint32_t cl_rank() {
    uint32_t r; asm("mov.u32 %0, %%cluster_ctarank;" : "=r"(r)); return r;
}
__device__ __forceinline__ uint32_t cl_map(uint32_t addr, uint32_t rank) {
    uint32_t r; asm("mapa.shared::cluster.u32 %0, %1, %2;" : "=r"(r) : "r"(addr), "r"(rank)); return r;
}
__device__ __forceinline__ void st_cl_f32(uint32_t addr, float v) {
    asm volatile("st.shared::cluster.f32 [%0], %1;" :: "r"(addr), "f"(v) : "memory");
}
__device__ __forceinline__ void cl_arrive() {
    asm volatile("barrier.cluster.arrive.aligned;" ::: "memory");
}
__device__ __forceinline__ void cl_wait() {
    asm volatile("barrier.cluster.wait.aligned;" ::: "memory");
}
__device__ __forceinline__ void cl_sync() { cl_arrive(); cl_wait(); }

__device__ __forceinline__ float fast_sigmoid(float x) {
    return 1.f / (1.f + __expf(-x));
}
__device__ __forceinline__ float fast_tanh(float x) {
    // 1 - 2/(1+e^{2x}) : exact limits at +-inf, ~2ulp from __expf
    return 1.f - __fdividef(2.f, 1.f + __expf(2.f * x));
}

// ---------------- input-gate GEMM (FFMA2) ----------------
// C[r,g] = sum_k A[r,k] * W[g,k] + bias[g]
// Tile 128(rows) x 64(gates), BK=16, 256 threads, 8x4 register blocking via f32x2.
__global__ __launch_bounds__(256) void gemm_gates(
    const float* __restrict__ A, const float* __restrict__ W,
    const float* __restrict__ bias, float* __restrict__ C)
{
    __shared__ float As[16 * 132];  // [k][row], padded
    __shared__ float Ws[16 * 68];   // [k][g],   padded (k*68 floats = 272B, 16B aligned)

    const int tid  = threadIdx.x;
    const int row0 = blockIdx.y * 128;
    const int g0   = blockIdx.x * 64;
    const int lr   = tid >> 2;
    const int kq   = tid & 3;
    const int tx   = tid & 15;
    const int ty   = tid >> 4;

    u64t acc0[8], acc1[8];   // [row i][col pair {j0j1}], [{j2j3}]
#pragma unroll
    for (int i = 0; i < 8; ++i) { acc0[i] = 0ull; acc1[i] = 0ull; }

    for (int k0 = 0; k0 < 256; k0 += 16) {
        float4 a0 = *(const float4*)(A + (size_t)(row0 + lr)      * 256 + k0 + kq * 4);
        float4 a1 = *(const float4*)(A + (size_t)(row0 + lr + 64) * 256 + k0 + kq * 4);
        float4 w0 = *(const float4*)(W + (size_t)(g0 + lr)        * 256 + k0 + kq * 4);
        __syncthreads();
        As[(kq*4+0)*132 + lr] = a0.x;
        As[(kq*4+1)*132 + lr] = a0.y;
        As[(kq*4+2)*132 + lr] = a0.z;
        As[(kq*4+3)*132 + lr] = a0.w;
        As[(kq*4+0)*132 + lr + 64] = a1.x;
        As[(kq*4+1)*132 + lr + 64] = a1.y;
        As[(kq*4+2)*132 + lr + 64] = a1.z;
        As[(kq*4+3)*132 + lr + 64] = a1.w;
        Ws[(kq*4+0)*68 + lr] = w0.x;
        Ws[(kq*4+1)*68 + lr] = w0.y;
        Ws[(kq*4+2)*68 + lr] = w0.z;
        Ws[(kq*4+3)*68 + lr] = w0.w;
        __syncthreads();
#pragma unroll
        for (int k = 0; k < 16; ++k) {
            float ra[8];
            *(float4*)(ra)     = *(const float4*)(As + k*132 + ty*8);
            *(float4*)(ra + 4) = *(const float4*)(As + k*132 + ty*8 + 4);
            ulonglong2 rwv = *(const ulonglong2*)(Ws + k*68 + tx*4);
#pragma unroll
            for (int i = 0; i < 8; ++i) {
                u64t ai = pack2(ra[i], ra[i]);
                acc0[i] = ffma2(ai, rwv.x, acc0[i]);
                acc1[i] = ffma2(ai, rwv.y, acc1[i]);
            }
        }
    }
    float4 bv = *(const float4*)(bias + g0 + tx*4);
#pragma unroll
    for (int i = 0; i < 8; ++i) {
        float2 p0 = unpack2(acc0[i]);
        float2 p1 = unpack2(acc1[i]);
        float4 o;
        o.x = p0.x + bv.x; o.y = p0.y + bv.y;
        o.z = p1.x + bv.z; o.w = p1.y + bv.w;
        *(float4*)(C + (size_t)(row0 + ty*8 + i) * 768 + g0 + tx*4) = o;
    }
}

// ---------------- GRU recurrence (FFMA2 dots, split cluster barrier) ----------------
// Cluster of 4 CTAs owns 4 batch rows; CTA rank owns h columns [rank*64, rank*64+64).
// 192KB of w_hh stay in SMEM for all 1024 steps.
// Dot mapping: 384 threads = (gate 0..2) x (col-pair {c, c+32}, 32 pairs) x (k-quarter 0..3).
// Each thread: 2 cols x 4 rows x 64 k, packed-pair accumulation over k (fma.rn.f32x2).
__global__ __launch_bounds__(384, 1) __cluster_dims__(4, 1, 1)
void gru_rec(const float* __restrict__ gx, const float* __restrict__ Whh,
             const float* __restrict__ bhh, float* __restrict__ out,
             float* __restrict__ hid)
{
    extern __shared__ float smem[];
    float4* sW4 = (float4*)smem;        // [gate(3)][kchunk(64)][col(64)] float4 = 192KB
    float*  sH  = smem + 49152;         // double-buffered h: [2][4 rows][256]
    float*  sGh = smem + 51200;         // gh partials: [4 kq][3 gate][4 row][64 col] = 12KB

    const uint32_t rank = cl_rank();
    const int b0  = (blockIdx.x >> 2) * 4;
    const int tid = threadIdx.x;

    // one-time: this CTA's w_hh chunk -> SMEM as [g][kc][col] float4
    for (int idx = tid; idx < 12288; idx += 384) {
        int g  = idx >> 12;
        int kc = (idx >> 6) & 63;
        int j  = idx & 63;
        int grow = g * 256 + (int)rank * 64 + j;
        sW4[idx] = ((const float4*)Whh)[grow * 64 + kc];
    }
    for (int i = tid; i < 2048; i += 384) sH[i] = 0.f;

    // dot-phase mapping
    const int kq = tid / 96;         // 0..3, warp-uniform (96 = 3 warps per kq)
    const int uu = tid % 96;
    const int gg = uu >> 5;          // gate 0..2 (warp-uniform)
    const int cp = uu & 31;
    const int c0 = cp, c1 = cp + 32;
    float biasA = 0.f, biasB = 0.f;
    if (kq == 0) {
        biasA = bhh[gg * 256 + (int)rank * 64 + c0];
        biasB = bhh[gg * 256 + (int)rank * 64 + c1];
    }

    // epilogue mapping (tid < 256): (row, col)
    const int erow = (tid >> 6) & 3;
    const int ecol = tid & 63;
    const size_t gxBase = ((size_t)(b0 + erow) * 1024) * 768 + rank * 64 + ecol;
    const size_t outBase = ((size_t)(b0 + erow) * 1024) * 256 + rank * 64 + ecol;

    // prefetch gx for t = 0
    float gxr = 0.f, gxz = 0.f, gxn = 0.f;
    if (tid < 256) {
        gxr = gx[gxBase];
        gxz = gx[gxBase + 256];
        gxn = gx[gxBase + 512];
    }

    cl_sync();  // weights + zeroed h visible cluster-wide

    float* hPrev = sH;
    float* hNext = sH + 1024;

    for (int t = 0; t < 1024; ++t) {
        // ---- dot phase: all 384 threads ----
        {
            const float4* wbase = sW4 + gg * 4096 + (kq * 16) * 64;
            const float*  hb    = hPrev + kq * 64;   // k-quarter offset (16 kc * 4 floats)
            u64t acc[8];
#pragma unroll
            for (int i = 0; i < 8; ++i) acc[i] = 0ull;
#pragma unroll
            for (int kk = 0; kk < 16; ++kk) {
                ulonglong2 wA = *(const ulonglong2*)(wbase + kk * 64 + c0);
                ulonglong2 wB = *(const ulonglong2*)(wbase + kk * 64 + c1);
#pragma unroll
                for (int r = 0; r < 4; ++r) {
                    ulonglong2 hv = *(const ulonglong2*)(hb + r * 256 + kk * 4);
                    acc[r]     = ffma2(wA.x, hv.x, acc[r]);
                    acc[r]     = ffma2(wA.y, hv.y, acc[r]);
                    acc[4 + r] = ffma2(wB.x, hv.x, acc[4 + r]);
                    acc[4 + r] = ffma2(wB.y, hv.y, acc[4 + r]);
                }
            }
            float* sg = sGh + kq * 768 + gg * 256;   // (g*4+r)*64 layout => gate block = 256
#pragma unroll
            for (int r = 0; r < 4; ++r) {
                float2 pa = unpack2(acc[r]);
                float2 pb = unpack2(acc[4 + r]);
                sg[r * 64 + c0] = pa.x + pa.y + biasA;
                sg[r * 64 + c1] = pb.x + pb.y + biasB;
            }
        }
        __syncthreads();

        // ---- epilogue: 256 threads ----
        if (tid < 256) {
            const int o = erow * 64 + ecol;
            float ghr = sGh[o]       + sGh[768 + o]       + sGh[1536 + o]       + sGh[2304 + o];
            float ghz = sGh[256 + o] + sGh[768 + 256 + o] + sGh[1536 + 256 + o] + sGh[2304 + 256 + o];
            float ghn = sGh[512 + o] + sGh[768 + 512 + o] + sGh[1536 + 512 + o] + sGh[2304 + 512 + o];

            float r  = fast_sigmoid(gxr + ghr);
            float z  = fast_sigmoid(gxz + ghz);
            float hp = hPrev[erow * 256 + rank * 64 + ecol];
            float n  = fast_tanh(fmaf(r, ghn, gxn));
            float hnew = fmaf(z, hp - n, n);   // (1-z)*n + z*hp

            out[outBase + (size_t)t * 256] = hnew;

            // new h element: local store + 3 remote DSMEM stores
            float* hdst = hNext + erow * 256 + rank * 64 + ecol;
            *hdst = hnew;
            uint32_t laddr = smem_u32(hdst);
#pragma unroll
            for (int pr = 0; pr < 4; ++pr)
                if (pr != (int)rank) st_cl_f32(cl_map(laddr, (uint32_t)pr), hnew);
        }
        cl_arrive();
        // prefetch gx for t+1 in the arrive->wait gap
        if (t + 1 < 1024 && tid < 256) {
            size_t base = gxBase + (size_t)(t + 1) * 768;
            gxr = gx[base];
            gxz = gx[base + 256];
            gxn = gx[base + 512];
        }
        cl_wait();
        float* tmpp = hPrev; hPrev = hNext; hNext = tmpp;
    }

    if (tid < 256)
        hid[(size_t)(b0 + erow) * 256 + rank * 64 + ecol] =
            hPrev[erow * 256 + rank * 64 + ecol];
}

// ---------------- launch ----------------
extern "C" void kernel_launch(void* const* d_in, const int* in_sizes, int n_in,
                              void* d_out, int out_size)
{
    const float* X      = (const float*)d_in[0];
    const float* w_ih_0 = (const float*)d_in[1];
    const float* w_hh_0 = (const float*)d_in[2];
    const float* b_ih_0 = (const float*)d_in[3];
    const float* b_hh_0 = (const float*)d_in[4];
    const float* w_ih_1 = (const float*)d_in[5];
    const float* w_hh_1 = (const float*)d_in[6];
    const float* b_ih_1 = (const float*)d_in[7];
    const float* b_hh_1 = (const float*)d_in[8];

    float* out1 = (float*)d_out;                       // [B,T,M]
    float* hid  = out1 + (size_t)ROWS * Mm;            // [2,B,M]

    float* gx = nullptr;
    float* o0 = nullptr;
    cudaGetSymbolAddress((void**)&gx, g_gx);
    cudaGetSymbolAddress((void**)&o0, g_out0);

    const size_t REC_SMEM = 217088;  // 192KB weights + 8KB h + 12KB gh staging
    cudaFuncSetAttribute(gru_rec, cudaFuncAttributeMaxDynamicSharedMemorySize,
                         (int)REC_SMEM);

    dim3 ggrid(12, 1024);  // gates x row-tiles

    // layer 0
    gemm_gates<<<ggrid, 256>>>(X, w_ih_0, b_ih_0, gx);
    gru_rec<<<128, 384, REC_SMEM>>>(gx, w_hh_0, b_hh_0, o0, hid);
    // layer 1
    gemm_gates<<<ggrid, 256>>>(o0, w_ih_1, b_ih_1, gx);
    gru_rec<<<128, 384, REC_SMEM>>>(gx, w_hh_1, b_hh_1, out1, hid + (size_t)Bb * Mm);
}

// round 9
// speedup vs baseline: 1.3937x; 1.1311x over previous
#include <cuda_runtime.h>
#include <cuda_bf16.h>
#include <cstdint>
#include <math.h>

#define Bb 128
#define Tt 1024
#define Nn 256
#define Mm 256
#define Gg 768
#define ROWS (Bb*Tt)

// Scratch (allocation-free rule: __device__ globals)
__device__ float g_gx[(size_t)ROWS * Gg];    // input-gate activations
__device__ float g_out0[(size_t)ROWS * Mm];  // layer-0 output

typedef unsigned long long u64t;

// ---------------- packed f32x2 helpers ----------------
__device__ __forceinline__ u64t ffma2(u64t a, u64t b, u64t c) {
    u64t d;
    asm("fma.rn.f32x2 %0, %1, %2, %3;" : "=l"(d) : "l"(a), "l"(b), "l"(c));
    return d;
}
__device__ __forceinline__ float2 unpack2(u64t v) {
    float2 r; asm("mov.b64 {%0, %1}, %2;" : "=f"(r.x), "=f"(r.y) : "l"(v)); return r;
}

// ---------------- cluster / DSMEM helpers ----------------
__device__ __forceinline__ uint32_t smem_u32(const void* p) {
    uint32_t a;
    asm("{ .reg .u64 t; cvta.to.shared.u64 t, %1; cvt.u32.u64 %0, t; }" : "=r"(a) : "l"(p));
    return a;
}
__device__ __forceinline__ uint32_t cl_rank() {
    uint32_t r; asm("mov.u32 %0, %%cluster_ctarank;" : "=r"(r)); return r;
}
__device__ __forceinline__ uint32_t cl_map(uint32_t addr, uint32_t rank) {
    uint32_t r; asm("mapa.shared::cluster.u32 %0, %1, %2;" : "=r"(r) : "r"(addr), "r"(rank)); return r;
}
__device__ __forceinline__ void st_cl_f32(uint32_t addr, float v) {
    asm volatile("st.shared::cluster.f32 [%0], %1;" :: "r"(addr), "f"(v) : "memory");
}
__device__ __forceinline__ void cl_sync() {
    asm volatile("barrier.cluster.arrive.aligned;" ::: "memory");
    asm volatile("barrier.cluster.wait.aligned;" ::: "memory");
}

// ---------------- mbarrier helpers ----------------
__device__ __forceinline__ void mbar_init(uint32_t a, uint32_t cnt) {
    asm volatile("mbarrier.init.shared.b64 [%0], %1;" :: "r"(a), "r"(cnt) : "memory");
}
__device__ __forceinline__ void mbar_arrive_cluster(uint32_t local_addr, uint32_t pr) {
    asm volatile(
        "{\n\t.reg .b32 ra;\n\t"
        "mapa.shared::cluster.u32 ra, %0, %1;\n\t"
        "mbarrier.arrive.shared::cluster.b64 _, [ra];\n\t}"
        :: "r"(local_addr), "r"(pr) : "memory");
}
__device__ __forceinline__ void mbar_wait_parity_cluster(uint32_t a, uint32_t parity) {
    asm volatile(
        "{\n\t.reg .pred P1;\n\t"
        "WL_%=:\n\t"
        "mbarrier.try_wait.parity.acquire.cluster.shared::cta.b64 P1, [%0], %1, 0x989680;\n\t"
        "@P1 bra.uni WD_%=;\n\t"
        "bra.uni WL_%=;\n\t"
        "WD_%=:\n\t}"
        :: "r"(a), "r"(parity) : "memory");
}

__device__ __forceinline__ float fast_sigmoid(float x) {
    return 1.f / (1.f + __expf(-x));
}
__device__ __forceinline__ float fast_tanh(float x) {
    return 1.f - __fdividef(2.f, 1.f + __expf(2.f * x));
}

// ---------------- warp-MMA helpers (baseline ISA, no tcgen05) ----------------
__device__ __forceinline__ void ldsm4(uint32_t r[4], uint32_t addr) {
    asm volatile("ldmatrix.sync.aligned.m8n8.x4.shared.b16 {%0,%1,%2,%3}, [%4];"
                 : "=r"(r[0]), "=r"(r[1]), "=r"(r[2]), "=r"(r[3]) : "r"(addr));
}
__device__ __forceinline__ void hmma(float4& d, const uint32_t a[4], const uint32_t* b) {
    asm volatile("mma.sync.aligned.m16n8k16.row.col.f32.bf16.bf16.f32 "
                 "{%0,%1,%2,%3}, {%4,%5,%6,%7}, {%8,%9}, {%0,%1,%2,%3};"
                 : "+f"(d.x), "+f"(d.y), "+f"(d.z), "+f"(d.w)
                 : "r"(a[0]), "r"(a[1]), "r"(a[2]), "r"(a[3]), "r"(b[0]), "r"(b[1]));
}

// split fp32 -> bf16 hi + bf16 residual, pack pairs into u32
__device__ __forceinline__ void split2(float x, float y, uint32_t& hi, uint32_t& lo) {
    __nv_bfloat16 hx = __float2bfloat16(x);
    __nv_bfloat16 hy = __float2bfloat16(y);
    __nv_bfloat16 lx = __float2bfloat16(x - __bfloat162float(hx));
    __nv_bfloat16 ly = __float2bfloat16(y - __bfloat162float(hy));
    hi = (uint32_t)*(uint16_t*)&hx | ((uint32_t)*(uint16_t*)&hy << 16);
    lo = (uint32_t)*(uint16_t*)&lx | ((uint32_t)*(uint16_t*)&ly << 16);
}

// ---------------- input-gate GEMM via mma.sync bf16x3 (fp32-accurate) ----------------
// C[r,g] = sum_k A[r,k]*W[g,k] + bias[g]
// CTA: 256 thr (8 warps, 4m x 2n), tile 128 rows x 64 gates, k-step 16.
// W tile converted to bf16 hi/lo ONCE per CTA, resident in SMEM (padded stride 528B).
// A tile converted per k-step (padded stride 48B), next k-step LDG prefetched in regs.
#define SW_HI   0
#define SW_LO   33792
#define SA_HI   67584
#define SA_LO   73728
#define SBIAS   79872
#define SM_GEMM 80128
#define WSTRIDE 528   // bytes per gate row (256 bf16 + 8 pad)

__global__ __launch_bounds__(256, 2) void gemm_hmma(
    const float* __restrict__ A, const float* __restrict__ W,
    const float* __restrict__ bias, float* __restrict__ C)
{
    extern __shared__ char sm[];
    const uint32_t sb = smem_u32(sm);
    const int tid  = threadIdx.x;
    const int lane = tid & 31, warp = tid >> 5;
    const int wm = warp >> 1, wn = warp & 1;
    const int g0 = blockIdx.x * 64;

    // ---- one-time: W[g0..g0+64][0..256] fp32 -> bf16 hi/lo SMEM ----
    {
        const int r = tid >> 2, kq = tid & 3;
        const float4* wp = (const float4*)(W + (size_t)(g0 + r) * 256 + kq * 64);
        char* dh = sm + SW_HI + r * WSTRIDE + kq * 128;
        char* dl = sm + SW_LO + r * WSTRIDE + kq * 128;
#pragma unroll
        for (int kk = 0; kk < 16; ++kk) {
            float4 v = wp[kk];
            uint2 h, l;
            split2(v.x, v.y, h.x, l.x);
            split2(v.z, v.w, h.y, l.y);
            *(uint2*)(dh + kk * 8) = h;
            *(uint2*)(dl + kk * 8) = l;
        }
    }
    if (tid < 64) ((float*)(sm + SBIAS))[tid] = bias[g0 + tid];

    // ldmatrix lane-address components
    const int lq = lane >> 3, l8 = lane & 7;
    const uint32_t arow = (uint32_t)((lq & 1) * 8 + l8);   // A: quad -> row
    const uint32_t akh  = (uint32_t)((lq >> 1) * 16);      // A: quad -> k-half bytes
    const uint32_t bgat = (uint32_t)((lq >> 1) * 8 + l8);  // B: quad -> gate
    const uint32_t bkh  = (uint32_t)((lq & 1) * 8);        // B: quad -> k-half
    const int grp = lane >> 2, tig = lane & 3;

    __syncthreads();

    for (int rt = blockIdx.y; rt < 1024; rt += 24) {
        const float* Ab = A + (size_t)rt * 128 * 256;
        const int prow = tid >> 1, phalf = tid & 1;

        // prefetch k-step 0
        float4 pa0, pa1;
        {
            const float4* ap = (const float4*)(Ab + (size_t)prow * 256 + phalf * 8);
            pa0 = ap[0]; pa1 = ap[1];
        }

        float4 d[2][4];
#pragma unroll
        for (int i = 0; i < 2; ++i)
#pragma unroll
            for (int j = 0; j < 4; ++j) d[i][j] = float4{0.f, 0.f, 0.f, 0.f};

        for (int ks = 0; ks < 16; ++ks) {
            __syncthreads();   // previous ldmatrix done, A smem reusable
            {
                uint4 h, l;
                split2(pa0.x, pa0.y, h.x, l.x);
                split2(pa0.z, pa0.w, h.y, l.y);
                split2(pa1.x, pa1.y, h.z, l.z);
                split2(pa1.z, pa1.w, h.w, l.w);
                *(uint4*)(sm + SA_HI + prow * 48 + phalf * 16) = h;
                *(uint4*)(sm + SA_LO + prow * 48 + phalf * 16) = l;
            }
            __syncthreads();
            if (ks + 1 < 16) {
                const float4* ap = (const float4*)(Ab + (size_t)prow * 256 + (ks + 1) * 16 + phalf * 8);
                pa0 = ap[0]; pa1 = ap[1];
            }

            // fragments
            uint32_t ah[2][4], al[2][4], bhr[2][4], blr[2][4];
#pragma unroll
            for (int mf = 0; mf < 2; ++mf) {
                uint32_t off = (uint32_t)((wm * 32 + mf * 16 + arow) * 48) + akh;
                ldsm4(ah[mf], sb + SA_HI + off);
                ldsm4(al[mf], sb + SA_LO + off);
            }
#pragma unroll
            for (int bp = 0; bp < 2; ++bp) {
                uint32_t off = (uint32_t)((wn * 32 + bp * 16 + bgat) * WSTRIDE)
                             + (uint32_t)((ks * 16 + bkh) * 2);
                ldsm4(bhr[bp], sb + SW_HI + off);
                ldsm4(blr[bp], sb + SW_LO + off);
            }
            // 24 HMMA: Ah*Wh + Ah*Wl + Al*Wh
#pragma unroll
            for (int mf = 0; mf < 2; ++mf)
#pragma unroll
                for (int nf = 0; nf < 4; ++nf) {
                    const uint32_t* bh = &bhr[nf >> 1][(nf & 1) * 2];
                    const uint32_t* bl = &blr[nf >> 1][(nf & 1) * 2];
                    hmma(d[mf][nf], ah[mf], bh);
                    hmma(d[mf][nf], ah[mf], bl);
                    hmma(d[mf][nf], al[mf], bh);
                }
        }

        // epilogue: + bias, store fp32
        const float* bs = (const float*)(sm + SBIAS);
#pragma unroll
        for (int mf = 0; mf < 2; ++mf) {
            size_t row = (size_t)rt * 128 + wm * 32 + mf * 16 + grp;
#pragma unroll
            for (int nf = 0; nf < 4; ++nf) {
                int gc = wn * 32 + nf * 8 + 2 * tig;
                float bx = bs[gc], by = bs[gc + 1];
                float4 v = d[mf][nf];
                *(float2*)(C + row * 768 + g0 + gc)       = float2{v.x + bx, v.y + by};
                *(float2*)(C + (row + 8) * 768 + g0 + gc) = float2{v.z + bx, v.w + by};
            }
        }
    }
}

// ---------------- GRU recurrence (FFMA2 dots, mbarrier cluster step-sync) ----------------
// Cluster of 4 CTAs owns 4 batch rows; CTA rank owns h columns [rank*64, rank*64+64).
// 192KB of w_hh stay in SMEM for all 1024 steps.
__global__ __launch_bounds__(384, 1) __cluster_dims__(4, 1, 1)
void gru_rec(const float* __restrict__ gx, const float* __restrict__ Whh,
             const float* __restrict__ bhh, float* __restrict__ out,
             float* __restrict__ hid)
{
    extern __shared__ float smem[];
    float4* sW4 = (float4*)smem;        // [gate(3)][kchunk(64)][col(64)] float4 = 192KB
    float*  sH  = smem + 49152;         // double-buffered h: [2][4 rows][256]
    float*  sGh = smem + 51200;         // gh partials: [4 kq][3 gate][4 row][64 col] = 12KB
    const uint32_t mbarA = smem_u32(smem) + 217088;   // step mbarrier

    const uint32_t rank = cl_rank();
    const int b0  = (blockIdx.x >> 2) * 4;
    const int tid = threadIdx.x;

    if (tid == 0) mbar_init(mbarA, 4);

    for (int idx = tid; idx < 12288; idx += 384) {
        int g  = idx >> 12;
        int kc = (idx >> 6) & 63;
        int j  = idx & 63;
        int grow = g * 256 + (int)rank * 64 + j;
        sW4[idx] = ((const float4*)Whh)[grow * 64 + kc];
    }
    for (int i = tid; i < 2048; i += 384) sH[i] = 0.f;

    const int kq = tid / 96;
    const int uu = tid % 96;
    const int gg = uu >> 5;
    const int cp = uu & 31;
    const int c0 = cp, c1 = cp + 32;
    float biasA = 0.f, biasB = 0.f;
    if (kq == 0) {
        biasA = bhh[gg * 256 + (int)rank * 64 + c0];
        biasB = bhh[gg * 256 + (int)rank * 64 + c1];
    }

    const int erow = (tid >> 6) & 3;
    const int ecol = tid & 63;
    const size_t gxBase  = ((size_t)(b0 + erow) * 1024) * 768 + rank * 64 + ecol;
    const size_t outBase = ((size_t)(b0 + erow) * 1024) * 256 + rank * 64 + ecol;

    float gxr = 0.f, gxz = 0.f, gxn = 0.f;
    if (tid < 256) {
        gxr = gx[gxBase];
        gxz = gx[gxBase + 256];
        gxn = gx[gxBase + 512];
    }

    cl_sync();  // weights, zeroed h, mbarrier inits visible cluster-wide

    float* hPrev = sH;
    float* hNext = sH + 1024;

    for (int t = 0; t < 1024; ++t) {
        // ---- dot phase: all 384 threads ----
        {
            const float4* wbase = sW4 + gg * 4096 + (kq * 16) * 64;
            const float*  hb    = hPrev + kq * 64;
            u64t acc[8];
#pragma unroll
            for (int i = 0; i < 8; ++i) acc[i] = 0ull;
#pragma unroll
            for (int kk = 0; kk < 16; ++kk) {
                ulonglong2 wA = *(const ulonglong2*)(wbase + kk * 64 + c0);
                ulonglong2 wB = *(const ulonglong2*)(wbase + kk * 64 + c1);
#pragma unroll
                for (int r = 0; r < 4; ++r) {
                    ulonglong2 hv = *(const ulonglong2*)(hb + r * 256 + kk * 4);
                    acc[r]     = ffma2(wA.x, hv.x, acc[r]);
                    acc[r]     = ffma2(wA.y, hv.y, acc[r]);
                    acc[4 + r] = ffma2(wB.x, hv.x, acc[4 + r]);
                    acc[4 + r] = ffma2(wB.y, hv.y, acc[4 + r]);
                }
            }
            float* sg = sGh + kq * 768 + gg * 256;
#pragma unroll
            for (int r = 0; r < 4; ++r) {
                float2 pa = unpack2(acc[r]);
                float2 pb = unpack2(acc[4 + r]);
                sg[r * 64 + c0] = pa.x + pa.y + biasA;
                sg[r * 64 + c1] = pb.x + pb.y + biasB;
            }
        }
        __syncthreads();

        // ---- epilogue: 256 threads ----
        float hnew = 0.f;
        if (tid < 256) {
            const int o = erow * 64 + ecol;
            float ghr = sGh[o]       + sGh[768 + o]       + sGh[1536 + o]       + sGh[2304 + o];
            float ghz = sGh[256 + o] + sGh[768 + 256 + o] + sGh[1536 + 256 + o] + sGh[2304 + 256 + o];
            float ghn = sGh[512 + o] + sGh[768 + 512 + o] + sGh[1536 + 512 + o] + sGh[2304 + 512 + o];

            float r  = fast_sigmoid(gxr + ghr);
            float z  = fast_sigmoid(gxz + ghz);
            float hp = hPrev[erow * 256 + rank * 64 + ecol];
            float n  = fast_tanh(fmaf(r, ghn, gxn));
            hnew = fmaf(z, hp - n, n);   // (1-z)*n + z*hp

            float* hdst = hNext + erow * 256 + rank * 64 + ecol;
            *hdst = hnew;
            uint32_t laddr = smem_u32(hdst);
#pragma unroll
            for (int pr = 0; pr < 4; ++pr)
                if (pr != (int)rank) st_cl_f32(cl_map(laddr, (uint32_t)pr), hnew);
        }
        __syncthreads();  // all threads' h stores issued before the signal

        if (tid == 0) {
            asm volatile("fence.acq_rel.cluster;" ::: "memory");  // publish DSMEM writes
#pragma unroll
            for (int pr = 0; pr < 4; ++pr) mbar_arrive_cluster(mbarA, (uint32_t)pr);
        }
        // hide arrive->wait gap: out store + next-step gx prefetch
        if (tid < 256) {
            out[outBase + (size_t)t * 256] = hnew;
            if (t + 1 < 1024) {
                size_t base = gxBase + (size_t)(t + 1) * 768;
                gxr = gx[base];
                gxz = gx[base + 256];
                gxn = gx[base + 512];
            }
        }
        mbar_wait_parity_cluster(mbarA, (uint32_t)(t & 1));
        float* tmpp = hPrev; hPrev = hNext; hNext = tmpp;
    }

    if (tid < 256)
        hid[(size_t)(b0 + erow) * 256 + rank * 64 + ecol] =
            hPrev[erow * 256 + rank * 64 + ecol];
    cl_sync();  // no CTA exits while peers may still target its SMEM
}

// ---------------- launch ----------------
extern "C" void kernel_launch(void* const* d_in, const int* in_sizes, int n_in,
                              void* d_out, int out_size)
{
    const float* X      = (const float*)d_in[0];
    const float* w_ih_0 = (const float*)d_in[1];
    const float* w_hh_0 = (const float*)d_in[2];
    const float* b_ih_0 = (const float*)d_in[3];
    const float* b_hh_0 = (const float*)d_in[4];
    const float* w_ih_1 = (const float*)d_in[5];
    const float* w_hh_1 = (const float*)d_in[6];
    const float* b_ih_1 = (const float*)d_in[7];
    const float* b_hh_1 = (const float*)d_in[8];

    float* out1 = (float*)d_out;
    float* hid  = out1 + (size_t)ROWS * Mm;

    float *gx = nullptr, *o0 = nullptr;
    cudaGetSymbolAddress((void**)&gx, g_gx);
    cudaGetSymbolAddress((void**)&o0, g_out0);

    const size_t REC_SMEM = 217104;  // 192KB weights + 8KB h + 12KB gh + mbar
    cudaFuncSetAttribute(gru_rec, cudaFuncAttributeMaxDynamicSharedMemorySize, (int)REC_SMEM);
    cudaFuncSetAttribute(gemm_hmma, cudaFuncAttributeMaxDynamicSharedMemorySize, SM_GEMM);

    dim3 ggrid(12, 24);   // 12 gate-tiles x 24 row-streams, ~2 CTAs/SM, one wave

    // layer 0
    gemm_hmma<<<ggrid, 256, SM_GEMM>>>(X, w_ih_0, b_ih_0, gx);
    gru_rec<<<128, 384, REC_SMEM>>>(gx, w_hh_0, b_hh_0, o0, hid);
    // layer 1
    gemm_hmma<<<ggrid, 256, SM_GEMM>>>(o0, w_ih_1, b_ih_1, gx);
    gru_rec<<<128, 384, REC_SMEM>>>(gx, w_hh_1, b_hh_1, out1, hid + (size_t)Bb * Mm);
}

// round 10
// speedup vs baseline: 1.5857x; 1.1378x over previous
#include <cuda_runtime.h>
#include <cuda_bf16.h>
#include <cstdint>
#include <math.h>

#define Bb 128
#define Tt 1024
#define Nn 256
#define Mm 256
#define Gg 768
#define ROWS (Bb*Tt)

// Scratch (allocation-free rule: __device__ globals)
__device__ float g_gx[(size_t)ROWS * Gg];    // input-gate activations
__device__ float g_out0[(size_t)ROWS * Mm];  // layer-0 output

typedef unsigned long long u64t;

// ---------------- packed f32x2 helpers ----------------
__device__ __forceinline__ u64t ffma2(u64t a, u64t b, u64t c) {
    u64t d;
    asm("fma.rn.f32x2 %0, %1, %2, %3;" : "=l"(d) : "l"(a), "l"(b), "l"(c));
    return d;
}
__device__ __forceinline__ float2 unpack2(u64t v) {
    float2 r; asm("mov.b64 {%0, %1}, %2;" : "=f"(r.x), "=f"(r.y) : "l"(v)); return r;
}

// ---------------- cluster / DSMEM helpers ----------------
__device__ __forceinline__ uint32_t smem_u32(const void* p) {
    uint32_t a;
    asm("{ .reg .u64 t; cvta.to.shared.u64 t, %1; cvt.u32.u64 %0, t; }" : "=r"(a) : "l"(p));
    return a;
}
__device__ __forceinline__ uint32_t cl_rank() {
    uint32_t r; asm("mov.u32 %0, %%cluster_ctarank;" : "=r"(r)); return r;
}
__device__ __forceinline__ uint32_t cl_map(uint32_t addr, uint32_t rank) {
    uint32_t r; asm("mapa.shared::cluster.u32 %0, %1, %2;" : "=r"(r) : "r"(addr), "r"(rank)); return r;
}
__device__ __forceinline__ void st_cl_f32(uint32_t addr, float v) {
    asm volatile("st.shared::cluster.f32 [%0], %1;" :: "r"(addr), "f"(v) : "memory");
}
__device__ __forceinline__ void cl_sync() {
    asm volatile("barrier.cluster.arrive.aligned;" ::: "memory");
    asm volatile("barrier.cluster.wait.aligned;" ::: "memory");
}

// ---------------- mbarrier helpers ----------------
__device__ __forceinline__ void mbar_init(uint32_t a, uint32_t cnt) {
    asm volatile("mbarrier.init.shared.b64 [%0], %1;" :: "r"(a), "r"(cnt) : "memory");
}
__device__ __forceinline__ void mbar_arrive_cluster(uint32_t local_addr, uint32_t pr) {
    asm volatile(
        "{\n\t.reg .b32 ra;\n\t"
        "mapa.shared::cluster.u32 ra, %0, %1;\n\t"
        "mbarrier.arrive.shared::cluster.b64 _, [ra];\n\t}"
        :: "r"(local_addr), "r"(pr) : "memory");
}
__device__ __forceinline__ void mbar_wait_parity_cluster(uint32_t a, uint32_t parity) {
    asm volatile(
        "{\n\t.reg .pred P1;\n\t"
        "WL_%=:\n\t"
        "mbarrier.try_wait.parity.acquire.cluster.shared::cta.b64 P1, [%0], %1, 0x989680;\n\t"
        "@P1 bra.uni WD_%=;\n\t"
        "bra.uni WL_%=;\n\t"
        "WD_%=:\n\t}"
        :: "r"(a), "r"(parity) : "memory");
}

__device__ __forceinline__ float fast_sigmoid(float x) {
    return 1.f / (1.f + __expf(-x));
}
__device__ __forceinline__ float fast_tanh(float x) {
    return 1.f - __fdividef(2.f, 1.f + __expf(2.f * x));
}

// ---------------- warp-MMA helpers (baseline ISA, no tcgen05) ----------------
__device__ __forceinline__ void ldsm4(uint32_t r[4], uint32_t addr) {
    asm volatile("ldmatrix.sync.aligned.m8n8.x4.shared.b16 {%0,%1,%2,%3}, [%4];"
                 : "=r"(r[0]), "=r"(r[1]), "=r"(r[2]), "=r"(r[3]) : "r"(addr));
}
__device__ __forceinline__ void hmma(float4& d, const uint32_t a[4], const uint32_t* b) {
    asm volatile("mma.sync.aligned.m16n8k16.row.col.f32.bf16.bf16.f32 "
                 "{%0,%1,%2,%3}, {%4,%5,%6,%7}, {%8,%9}, {%0,%1,%2,%3};"
                 : "+f"(d.x), "+f"(d.y), "+f"(d.z), "+f"(d.w)
                 : "r"(a[0]), "r"(a[1]), "r"(a[2]), "r"(a[3]), "r"(b[0]), "r"(b[1]));
}

// split fp32 -> bf16 hi + bf16 residual, pack pairs into u32
__device__ __forceinline__ void split2(float x, float y, uint32_t& hi, uint32_t& lo) {
    __nv_bfloat16 hx = __float2bfloat16(x);
    __nv_bfloat16 hy = __float2bfloat16(y);
    __nv_bfloat16 lx = __float2bfloat16(x - __bfloat162float(hx));
    __nv_bfloat16 ly = __float2bfloat16(y - __bfloat162float(hy));
    hi = (uint32_t)*(uint16_t*)&hx | ((uint32_t)*(uint16_t*)&hy << 16);
    lo = (uint32_t)*(uint16_t*)&lx | ((uint32_t)*(uint16_t*)&ly << 16);
}

// ---------------- input-gate GEMM via mma.sync bf16x3 (fp32-accurate) ----------------
#define SW_HI   0
#define SW_LO   33792
#define SA_HI   67584
#define SA_LO   73728
#define SBIAS   79872
#define SM_GEMM 80128
#define WSTRIDE 528   // bytes per gate row (256 bf16 + 8 pad)

__global__ __launch_bounds__(256, 2) void gemm_hmma(
    const float* __restrict__ A, const float* __restrict__ W,
    const float* __restrict__ bias, float* __restrict__ C)
{
    extern __shared__ char sm[];
    const uint32_t sb = smem_u32(sm);
    const int tid  = threadIdx.x;
    const int lane = tid & 31, warp = tid >> 5;
    const int wm = warp >> 1, wn = warp & 1;
    const int g0 = blockIdx.x * 64;

    // one-time: W tile fp32 -> bf16 hi/lo SMEM
    {
        const int r = tid >> 2, kq = tid & 3;
        const float4* wp = (const float4*)(W + (size_t)(g0 + r) * 256 + kq * 64);
        char* dh = sm + SW_HI + r * WSTRIDE + kq * 128;
        char* dl = sm + SW_LO + r * WSTRIDE + kq * 128;
#pragma unroll
        for (int kk = 0; kk < 16; ++kk) {
            float4 v = wp[kk];
            uint2 h, l;
            split2(v.x, v.y, h.x, l.x);
            split2(v.z, v.w, h.y, l.y);
            *(uint2*)(dh + kk * 8) = h;
            *(uint2*)(dl + kk * 8) = l;
        }
    }
    if (tid < 64) ((float*)(sm + SBIAS))[tid] = bias[g0 + tid];

    const int lq = lane >> 3, l8 = lane & 7;
    const uint32_t arow = (uint32_t)((lq & 1) * 8 + l8);
    const uint32_t akh  = (uint32_t)((lq >> 1) * 16);
    const uint32_t bgat = (uint32_t)((lq >> 1) * 8 + l8);
    const uint32_t bkh  = (uint32_t)((lq & 1) * 8);
    const int grp = lane >> 2, tig = lane & 3;

    __syncthreads();

    for (int rt = blockIdx.y; rt < 1024; rt += 24) {
        const float* Ab = A + (size_t)rt * 128 * 256;
        const int prow = tid >> 1, phalf = tid & 1;

        float4 pa0, pa1;
        {
            const float4* ap = (const float4*)(Ab + (size_t)prow * 256 + phalf * 8);
            pa0 = ap[0]; pa1 = ap[1];
        }

        float4 d[2][4];
#pragma unroll
        for (int i = 0; i < 2; ++i)
#pragma unroll
            for (int j = 0; j < 4; ++j) d[i][j] = float4{0.f, 0.f, 0.f, 0.f};

        for (int ks = 0; ks < 16; ++ks) {
            __syncthreads();
            {
                uint4 h, l;
                split2(pa0.x, pa0.y, h.x, l.x);
                split2(pa0.z, pa0.w, h.y, l.y);
                split2(pa1.x, pa1.y, h.z, l.z);
                split2(pa1.z, pa1.w, h.w, l.w);
                *(uint4*)(sm + SA_HI + prow * 48 + phalf * 16) = h;
                *(uint4*)(sm + SA_LO + prow * 48 + phalf * 16) = l;
            }
            __syncthreads();
            if (ks + 1 < 16) {
                const float4* ap = (const float4*)(Ab + (size_t)prow * 256 + (ks + 1) * 16 + phalf * 8);
                pa0 = ap[0]; pa1 = ap[1];
            }

            uint32_t ah[2][4], al[2][4], bhr[2][4], blr[2][4];
#pragma unroll
            for (int mf = 0; mf < 2; ++mf) {
                uint32_t off = (uint32_t)((wm * 32 + mf * 16 + arow) * 48) + akh;
                ldsm4(ah[mf], sb + SA_HI + off);
                ldsm4(al[mf], sb + SA_LO + off);
            }
#pragma unroll
            for (int bp = 0; bp < 2; ++bp) {
                uint32_t off = (uint32_t)((wn * 32 + bp * 16 + bgat) * WSTRIDE)
                             + (uint32_t)((ks * 16 + bkh) * 2);
                ldsm4(bhr[bp], sb + SW_HI + off);
                ldsm4(blr[bp], sb + SW_LO + off);
            }
#pragma unroll
            for (int mf = 0; mf < 2; ++mf)
#pragma unroll
                for (int nf = 0; nf < 4; ++nf) {
                    const uint32_t* bh = &bhr[nf >> 1][(nf & 1) * 2];
                    const uint32_t* bl = &blr[nf >> 1][(nf & 1) * 2];
                    hmma(d[mf][nf], ah[mf], bh);
                    hmma(d[mf][nf], ah[mf], bl);
                    hmma(d[mf][nf], al[mf], bh);
                }
        }

        const float* bs = (const float*)(sm + SBIAS);
#pragma unroll
        for (int mf = 0; mf < 2; ++mf) {
            size_t row = (size_t)rt * 128 + wm * 32 + mf * 16 + grp;
#pragma unroll
            for (int nf = 0; nf < 4; ++nf) {
                int gc = wn * 32 + nf * 8 + 2 * tig;
                float bx = bs[gc], by = bs[gc + 1];
                float4 v = d[mf][nf];
                *(float2*)(C + row * 768 + g0 + gc)       = float2{v.x + bx, v.y + by};
                *(float2*)(C + (row + 8) * 768 + g0 + gc) = float2{v.z + bx, v.w + by};
            }
        }
    }
}

// ---------------- GRU recurrence: register-resident half-weights ----------------
// Cluster of 4 CTAs owns 4 batch rows; CTA rank owns h columns [rank*64, +64).
// Each dot thread (gate g, cols {c, c+32}, k-quarter kq) holds the FIRST 32 k of its
// quarter in 16+16 u64 REGISTERS (96KB/CTA in regfile); the last 32 k stay in SMEM
// (96KB). Per-step crossbar: 768 (w) + 768 (h broadcast) vs 2300 before.
// mbarrier wait moved to top of dot and SKIPPED by warps with kq==rank (their h
// slice is produced locally) -> their FMA work overlaps the cluster barrier.
__global__ __launch_bounds__(384, 1) __cluster_dims__(4, 1, 1)
void gru_rec(const float* __restrict__ gx, const float* __restrict__ Whh,
             const float* __restrict__ bhh, float* __restrict__ out,
             float* __restrict__ hid)
{
    extern __shared__ float smem[];
    float4* sW4h = (float4*)smem;       // [gate(3)][kq(4)][kcl(8)][col(64)] float4 = 96KB
    float*  sH   = smem + 24576;        // double-buffered h: [2][4 rows][256] = 8KB
    float*  sGh  = smem + 26624;        // gh partials: [4 kq][3 gate][4 row][64 col] = 12KB
    const uint32_t mbarA = smem_u32(smem) + 159744;   // step mbarrier (39936 floats in)

    const uint32_t rank = cl_rank();
    const int b0  = (blockIdx.x >> 2) * 4;
    const int tid = threadIdx.x;

    if (tid == 0) mbar_init(mbarA, 4);

    // SMEM half: k 32..63 of each quarter -> [g][kq][kcl][col]
    for (int idx = tid; idx < 6144; idx += 384) {
        int g   = idx >> 11;
        int kqi = (idx >> 9) & 3;
        int kcl = (idx >> 6) & 7;
        int j   = idx & 63;
        int grow = g * 256 + (int)rank * 64 + j;
        int kc   = kqi * 16 + 8 + kcl;
        sW4h[idx] = ((const float4*)Whh)[grow * 64 + kc];
    }
    for (int i = tid; i < 2048; i += 384) sH[i] = 0.f;

    // dot-phase mapping
    const int kq = tid / 96;         // 0..3 (warp-uniform)
    const int uu = tid % 96;
    const int gg = uu >> 5;          // gate 0..2 (warp-uniform)
    const int cp = uu & 31;
    const int c0 = cp, c1 = cp + 32;
    float biasA = 0.f, biasB = 0.f;
    if (kq == 0) {
        biasA = bhh[gg * 256 + (int)rank * 64 + c0];
        biasB = bhh[gg * 256 + (int)rank * 64 + c1];
    }

    // register half: k 0..31 of this thread's quarter, for both cols
    u64t wrA[16], wrB[16];
    {
        const float* wbA = Whh + (size_t)(gg * 256 + (int)rank * 64 + c0) * 256 + kq * 64;
        const float* wbB = Whh + (size_t)(gg * 256 + (int)rank * 64 + c1) * 256 + kq * 64;
#pragma unroll
        for (int kk = 0; kk < 8; ++kk) {
            ulonglong2 a = *(const ulonglong2*)(wbA + kk * 4);
            ulonglong2 b = *(const ulonglong2*)(wbB + kk * 4);
            wrA[2 * kk] = a.x; wrA[2 * kk + 1] = a.y;
            wrB[2 * kk] = b.x; wrB[2 * kk + 1] = b.y;
        }
    }

    // epilogue mapping (tid < 256)
    const int erow = (tid >> 6) & 3;
    const int ecol = tid & 63;
    const size_t gxBase  = ((size_t)(b0 + erow) * 1024) * 768 + rank * 64 + ecol;
    const size_t outBase = ((size_t)(b0 + erow) * 1024) * 256 + rank * 64 + ecol;

    float gxr = 0.f, gxz = 0.f, gxn = 0.f;
    if (tid < 256) {
        gxr = gx[gxBase];
        gxz = gx[gxBase + 256];
        gxn = gx[gxBase + 512];
    }

    cl_sync();  // smem weights, zeroed h, mbarrier init visible cluster-wide

    const bool localq = (kq == (int)rank);

    for (int t = 0; t < 1024; ++t) {
        const float* hcur = sH + (t & 1) * 1024;
        float*       hnxt = sH + ((t + 1) & 1) * 1024;

        // remote-k warps must see step t's h from peer CTAs; local-k warps
        // proceed immediately (their h slice was written locally before sync2).
        if (t > 0 && !localq)
            mbar_wait_parity_cluster(mbarA, (uint32_t)((t - 1) & 1));

        // ---- dot phase ----
        {
            const float* hb = hcur + kq * 64;
            u64t acc[8];
#pragma unroll
            for (int i = 0; i < 8; ++i) acc[i] = 0ull;
            // part A: k 0..31 of quarter, weights from registers
#pragma unroll
            for (int kk = 0; kk < 8; ++kk) {
                u64t wax = wrA[2 * kk], way = wrA[2 * kk + 1];
                u64t wbx = wrB[2 * kk], wby = wrB[2 * kk + 1];
#pragma unroll
                for (int r = 0; r < 4; ++r) {
                    ulonglong2 hv = *(const ulonglong2*)(hb + r * 256 + kk * 4);
                    acc[r]     = ffma2(wax, hv.x, acc[r]);
                    acc[r]     = ffma2(way, hv.y, acc[r]);
                    acc[4 + r] = ffma2(wbx, hv.x, acc[4 + r]);
                    acc[4 + r] = ffma2(wby, hv.y, acc[4 + r]);
                }
            }
            // part B: k 32..63 of quarter, weights from SMEM
            const float4* wq = sW4h + (size_t)((gg * 4 + kq) * 8) * 64;
#pragma unroll
            for (int kk = 0; kk < 8; ++kk) {
                ulonglong2 wA = *(const ulonglong2*)(wq + kk * 64 + c0);
                ulonglong2 wB = *(const ulonglong2*)(wq + kk * 64 + c1);
#pragma unroll
                for (int r = 0; r < 4; ++r) {
                    ulonglong2 hv = *(const ulonglong2*)(hb + r * 256 + (8 + kk) * 4);
                    acc[r]     = ffma2(wA.x, hv.x, acc[r]);
                    acc[r]     = ffma2(wA.y, hv.y, acc[r]);
                    acc[4 + r] = ffma2(wB.x, hv.x, acc[4 + r]);
                    acc[4 + r] = ffma2(wB.y, hv.y, acc[4 + r]);
                }
            }
            float* sg = sGh + kq * 768 + gg * 256;
#pragma unroll
            for (int r = 0; r < 4; ++r) {
                float2 pa = unpack2(acc[r]);
                float2 pb = unpack2(acc[4 + r]);
                sg[r * 64 + c0] = pa.x + pa.y + biasA;
                sg[r * 64 + c1] = pb.x + pb.y + biasB;
            }
        }
        __syncthreads();

        // ---- epilogue: 256 threads ----
        float hnew = 0.f;
        if (tid < 256) {
            const int o = erow * 64 + ecol;
            float ghr = sGh[o]       + sGh[768 + o]       + sGh[1536 + o]       + sGh[2304 + o];
            float ghz = sGh[256 + o] + sGh[768 + 256 + o] + sGh[1536 + 256 + o] + sGh[2304 + 256 + o];
            float ghn = sGh[512 + o] + sGh[768 + 512 + o] + sGh[1536 + 512 + o] + sGh[2304 + 512 + o];

            float r  = fast_sigmoid(gxr + ghr);
            float z  = fast_sigmoid(gxz + ghz);
            float hp = hcur[erow * 256 + rank * 64 + ecol];
            float n  = fast_tanh(fmaf(r, ghn, gxn));
            hnew = fmaf(z, hp - n, n);   // (1-z)*n + z*hp

            float* hdst = hnxt + erow * 256 + rank * 64 + ecol;
            *hdst = hnew;
            uint32_t laddr = smem_u32(hdst);
#pragma unroll
            for (int pr = 0; pr < 4; ++pr)
                if (pr != (int)rank) st_cl_f32(cl_map(laddr, (uint32_t)pr), hnew);
        }
        __syncthreads();  // all threads' h stores issued before the signal

        if (tid == 0) {
            asm volatile("fence.acq_rel.cluster;" ::: "memory");  // publish DSMEM writes
#pragma unroll
            for (int pr = 0; pr < 4; ++pr) mbar_arrive_cluster(mbarA, (uint32_t)pr);
        }
        // hidden work: out store + next-step gx prefetch (no wait here; the wait
        // for this phase happens at the top of the next iteration, remote warps only)
        if (tid < 256) {
            out[outBase + (size_t)t * 256] = hnew;
            if (t + 1 < 1024) {
                size_t base = gxBase + (size_t)(t + 1) * 768;
                gxr = gx[base];
                gxz = gx[base + 256];
                gxn = gx[base + 512];
            }
        }
    }

    if (tid < 256)
        hid[(size_t)(b0 + erow) * 256 + rank * 64 + ecol] =
            sH[((1024 & 1)) * 1024 + erow * 256 + rank * 64 + ecol];
    cl_sync();  // no CTA exits while peers may still target its SMEM
}

// ---------------- launch ----------------
extern "C" void kernel_launch(void* const* d_in, const int* in_sizes, int n_in,
                              void* d_out, int out_size)
{
    const float* X      = (const float*)d_in[0];
    const float* w_ih_0 = (const float*)d_in[1];
    const float* w_hh_0 = (const float*)d_in[2];
    const float* b_ih_0 = (const float*)d_in[3];
    const float* b_hh_0 = (const float*)d_in[4];
    const float* w_ih_1 = (const float*)d_in[5];
    const float* w_hh_1 = (const float*)d_in[6];
    const float* b_ih_1 = (const float*)d_in[7];
    const float* b_hh_1 = (const float*)d_in[8];

    float* out1 = (float*)d_out;
    float* hid  = out1 + (size_t)ROWS * Mm;

    float *gx = nullptr, *o0 = nullptr;
    cudaGetSymbolAddress((void**)&gx, g_gx);
    cudaGetSymbolAddress((void**)&o0, g_out0);

    const size_t REC_SMEM = 159760;  // 96KB w-half + 8KB h + 12KB gh + pad + mbar
    cudaFuncSetAttribute(gru_rec, cudaFuncAttributeMaxDynamicSharedMemorySize, (int)REC_SMEM);
    cudaFuncSetAttribute(gemm_hmma, cudaFuncAttributeMaxDynamicSharedMemorySize, SM_GEMM);

    dim3 ggrid(12, 24);   // 12 gate-tiles x 24 row-streams, ~2 CTAs/SM

    // layer 0
    gemm_hmma<<<ggrid, 256, SM_GEMM>>>(X, w_ih_0, b_ih_0, gx);
    gru_rec<<<128, 384, REC_SMEM>>>(gx, w_hh_0, b_hh_0, o0, hid);
    // layer 1
    gemm_hmma<<<ggrid, 256, SM_GEMM>>>(o0, w_ih_1, b_ih_1, gx);
    gru_rec<<<128, 384, REC_SMEM>>>(gx, w_hh_1, b_hh_1, out1, hid + (size_t)Bb * Mm);
}